// round 9
// baseline (speedup 1.0000x reference)
#include <cuda_runtime.h>
#include <cuda_fp16.h>
#include <cstdint>

#define NN   100000
#define MPAD 100096            // 782 * 128
#define FEAT 256
#define NT   782
#define SPAD 72
#define EMAX 800000
#define NB   391               // ceil(NN/256)

// block ranges in k_pre
#define PRE_CVTX 25024         // MPAD*64/256
#define PRE_DEGI 3125
#define PRE_W12  512           // 2*256*256/256

// ---------------- device scratch ----------------
__device__ int   g_degi[NN];           // zero-init; k_off restores zeros
__device__ int   g_ctr;
__device__ float g_inv[NN];
__device__ int   g_off[NN];
__device__ int   g_end[NN];
__device__ int   g_cursor[NN];
__device__ int   g_srcl[EMAX];
__device__ __align__(16) __half g_yz[(size_t)MPAD * 512];
__device__ __align__(16) __half g_h[(size_t)MPAD * FEAT];
__device__ __align__(16) __half g_w[2][512 * 256];
__device__ __align__(16) __half g_w3[128 * 256];

// ---------------- helpers ----------------
__device__ __forceinline__ uint32_t smem_u32(const void* p) {
    uint32_t a;
    asm("{ .reg .u64 t; cvta.to.shared.u64 t, %1; cvt.u32.u64 %0, t; }" : "=r"(a) : "l"(p));
    return a;
}
__device__ __forceinline__ void cpa16(uint32_t dst, const void* src) {
    asm volatile("cp.async.cg.shared.global [%0], [%1], 16;" :: "r"(dst), "l"(src));
}
__device__ __forceinline__ void cvt_w_seg(const float* __restrict__ Ws,
                                          const float* __restrict__ Wn,
                                          int Nw, __half* __restrict__ w, int idx) {
    int n = idx >> 8, k = idx & 255;
    float v = (n < Nw) ? Ws[(size_t)k * Nw + n] : Wn[(size_t)k * Nw + (n - Nw)];
    w[idx] = __float2half_rn(v);
}

// ---------------- fused preprocessing: cvt_x | degi | cvt_w x3 ----------------
__global__ void k_pre(const float* __restrict__ x, const int* __restrict__ dst,
                      const float* __restrict__ Ws1, const float* __restrict__ Wn1,
                      const float* __restrict__ Ws2, const float* __restrict__ Wn2,
                      const float* __restrict__ Ws3, const float* __restrict__ Wn3,
                      int M, int E) {
    int b = blockIdx.x;
    int tid = threadIdx.x;
    if (b == 0 && tid == 0) g_ctr = 0;
    if (b < PRE_CVTX) {
        size_t i4 = (size_t)b * 256 + tid;
        int row = (int)(i4 >> 6);
        float4 v = make_float4(0.f, 0.f, 0.f, 0.f);
        if (row < M) v = reinterpret_cast<const float4*>(x)[i4];
        uint2 o;
        __half2 p0 = __float22half2_rn(make_float2(v.x, v.y));
        __half2 p1 = __float22half2_rn(make_float2(v.z, v.w));
        o.x = *reinterpret_cast<uint32_t*>(&p0);
        o.y = *reinterpret_cast<uint32_t*>(&p1);
        *reinterpret_cast<uint2*>(g_h + i4 * 4) = o;
        return;
    }
    b -= PRE_CVTX;
    if (b < PRE_DEGI) {
        int e = b * 256 + tid;
        if (e < E) atomicAdd(&g_degi[dst[e]], 1);
        return;
    }
    b -= PRE_DEGI;
    if (b < PRE_W12) { cvt_w_seg(Ws1, Wn1, 256, g_w[0], b * 256 + tid); return; }
    b -= PRE_W12;
    if (b < PRE_W12) { cvt_w_seg(Ws2, Wn2, 256, g_w[1], b * 256 + tid); return; }
    b -= PRE_W12;
    cvt_w_seg(Ws3, Wn3, 64, g_w3, b * 256 + tid);
}

// single-pass offsets: block scan + atomic range reservation
__global__ void k_off() {
    __shared__ int s[256];
    __shared__ int base;
    int i = blockIdx.x * 256 + threadIdx.x;
    int deg = (i < NN) ? g_degi[i] : 0;
    s[threadIdx.x] = deg;
    __syncthreads();
    for (int st = 1; st < 256; st <<= 1) {
        int add = (threadIdx.x >= st) ? s[threadIdx.x - st] : 0;
        __syncthreads();
        s[threadIdx.x] += add;
        __syncthreads();
    }
    if (threadIdx.x == 255) base = atomicAdd(&g_ctr, s[255]);
    __syncthreads();
    if (i < NN) {
        int beg = base + s[threadIdx.x] - deg;
        g_off[i] = beg;
        g_end[i] = beg + deg;
        g_cursor[i] = beg;
        g_inv[i] = 1.0f / fmaxf((float)deg, 1.0f);
        g_degi[i] = 0;                    // restore for next replay
    }
}
__global__ void k_fill(const int* __restrict__ src, const int* __restrict__ dst, int E) {
    int e = blockIdx.x * blockDim.x + threadIdx.x;
    if (e < E) {
        int pos = atomicAdd(&g_cursor[dst[e]], 1);
        g_srcl[pos] = src[e];
    }
}

// ---------------- fused gather + combine ----------------
__device__ __forceinline__ void acc8(float* acc, uint4 raw) {
    const __half2* hp = reinterpret_cast<const __half2*>(&raw);
#pragma unroll
    for (int q = 0; q < 4; q++) {
        float2 f = __half22float2(hp[q]);
        acc[q * 2 + 0] += f.x;
        acc[q * 2 + 1] += f.y;
    }
}
// layers 1/2: one warp per node, lane owns 8 cols of 256.
__global__ void k_gather(const float* __restrict__ bias, int M) {
    int wid  = threadIdx.x >> 5;
    int lane = threadIdx.x & 31;
    int node = blockIdx.x * (blockDim.x >> 5) + wid;
    if (node >= M) return;
    int beg = g_off[node], end = g_end[node];
    const __half* z = g_yz + 256 + lane * 8;
    float acc[8] = {0.f, 0.f, 0.f, 0.f, 0.f, 0.f, 0.f, 0.f};
    int j = beg;
    for (; j + 4 <= end; j += 4) {
        int s0 = g_srcl[j], s1 = g_srcl[j + 1];
        int s2 = g_srcl[j + 2], s3 = g_srcl[j + 3];
        uint4 r0 = *reinterpret_cast<const uint4*>(z + (size_t)s0 * 512);
        uint4 r1 = *reinterpret_cast<const uint4*>(z + (size_t)s1 * 512);
        uint4 r2 = *reinterpret_cast<const uint4*>(z + (size_t)s2 * 512);
        uint4 r3 = *reinterpret_cast<const uint4*>(z + (size_t)s3 * 512);
        acc8(acc, r0); acc8(acc, r1); acc8(acc, r2); acc8(acc, r3);
    }
    for (; j < end; j++) {
        int s0 = g_srcl[j];
        uint4 r0 = *reinterpret_cast<const uint4*>(z + (size_t)s0 * 512);
        acc8(acc, r0);
    }
    float inv = g_inv[node];
    uint4 rs = *reinterpret_cast<const uint4*>(g_yz + (size_t)node * 512 + lane * 8);
    const __half2* sp = reinterpret_cast<const __half2*>(&rs);
    float4 bva = *reinterpret_cast<const float4*>(bias + lane * 8);
    float4 bvb = *reinterpret_cast<const float4*>(bias + lane * 8 + 4);
    float bv[8] = {bva.x, bva.y, bva.z, bva.w, bvb.x, bvb.y, bvb.z, bvb.w};
    float v[8];
#pragma unroll
    for (int q = 0; q < 4; q++) {
        float2 ys = __half22float2(sp[q]);
        v[q * 2 + 0] = fmaxf(ys.x + inv * acc[q * 2 + 0] + bv[q * 2 + 0], 0.f);
        v[q * 2 + 1] = fmaxf(ys.y + inv * acc[q * 2 + 1] + bv[q * 2 + 1], 0.f);
    }
    uint4 o;
    __half2 p0 = __float22half2_rn(make_float2(v[0], v[1]));
    __half2 p1 = __float22half2_rn(make_float2(v[2], v[3]));
    __half2 p2 = __float22half2_rn(make_float2(v[4], v[5]));
    __half2 p3 = __float22half2_rn(make_float2(v[6], v[7]));
    o.x = *reinterpret_cast<uint32_t*>(&p0);
    o.y = *reinterpret_cast<uint32_t*>(&p1);
    o.z = *reinterpret_cast<uint32_t*>(&p2);
    o.w = *reinterpret_cast<uint32_t*>(&p3);
    *reinterpret_cast<uint4*>(g_h + (size_t)node * 256 + lane * 8) = o;
}
// layer 3: 8 lanes per node (4 nodes/warp), lane owns 8 of 64 cols, fp32 out.
__global__ void k_gather3(const float* __restrict__ bias, float* __restrict__ out, int M) {
    int wid  = threadIdx.x >> 5;
    int lane = threadIdx.x & 31;
    int node = (blockIdx.x * (blockDim.x >> 5) + wid) * 4 + (lane >> 3);
    int sub  = lane & 7;
    if (node >= M) return;
    int beg = g_off[node], end = g_end[node];
    const __half* z = g_yz + 64 + sub * 8;
    float acc[8] = {0.f, 0.f, 0.f, 0.f, 0.f, 0.f, 0.f, 0.f};
    int j = beg;
    for (; j + 4 <= end; j += 4) {
        int s0 = g_srcl[j], s1 = g_srcl[j + 1];
        int s2 = g_srcl[j + 2], s3 = g_srcl[j + 3];
        uint4 r0 = *reinterpret_cast<const uint4*>(z + (size_t)s0 * 128);
        uint4 r1 = *reinterpret_cast<const uint4*>(z + (size_t)s1 * 128);
        uint4 r2 = *reinterpret_cast<const uint4*>(z + (size_t)s2 * 128);
        uint4 r3 = *reinterpret_cast<const uint4*>(z + (size_t)s3 * 128);
        acc8(acc, r0); acc8(acc, r1); acc8(acc, r2); acc8(acc, r3);
    }
    for (; j < end; j++) {
        int s0 = g_srcl[j];
        uint4 r0 = *reinterpret_cast<const uint4*>(z + (size_t)s0 * 128);
        acc8(acc, r0);
    }
    float inv = g_inv[node];
    uint4 rs = *reinterpret_cast<const uint4*>(g_yz + (size_t)node * 128 + sub * 8);
    const __half2* sp = reinterpret_cast<const __half2*>(&rs);
    float4 bva = *reinterpret_cast<const float4*>(bias + sub * 8);
    float4 bvb = *reinterpret_cast<const float4*>(bias + sub * 8 + 4);
    float bv[8] = {bva.x, bva.y, bva.z, bva.w, bvb.x, bvb.y, bvb.z, bvb.w};
    float v[8];
#pragma unroll
    for (int q = 0; q < 4; q++) {
        float2 ys = __half22float2(sp[q]);
        v[q * 2 + 0] = ys.x + inv * acc[q * 2 + 0] + bv[q * 2 + 0];
        v[q * 2 + 1] = ys.y + inv * acc[q * 2 + 1] + bv[q * 2 + 1];
    }
    float* op = out + (size_t)node * 64 + sub * 8;
    *reinterpret_cast<float4*>(op)     = make_float4(v[0], v[1], v[2], v[3]);
    *reinterpret_cast<float4*>(op + 4) = make_float4(v[4], v[5], v[6], v[7]);
}

// ---------------- fp16 HMMA GEMM: 512 threads, 16 warps (4m x 4n), warp tile 32 x BN/4 ----------------
// CTA tile 128 x BN, BK=64, double-buffered cp.async.
template<int BN, int NF>
__global__ __launch_bounds__(512) void k_mma(
    const __half* __restrict__ A, const __half* __restrict__ B,
    __half* __restrict__ Y, int NOUT)
{
    extern __shared__ __half dyn[];
    constexpr int AS  = 128 * SPAD;
    constexpr int BS  = BN * SPAD;
    constexpr int STG = AS + BS;

    const int t    = threadIdx.x;
    const int wid  = t >> 5;
    const int lane = t & 31;
    const int wm0  = (wid >> 2) << 5;          // 0,32,64,96
    const int wn0  = (wid & 3) * (BN / 4);
    const int row0 = blockIdx.y * 128;
    const int col0 = blockIdx.x * BN;

    const int lr = t >> 3;                     // 0..63
    const int lc = (t & 7) << 3;               // 0..56

    float acc[2][NF][4];
#pragma unroll
    for (int mi = 0; mi < 2; mi++)
#pragma unroll
        for (int ni = 0; ni < NF; ni++)
#pragma unroll
            for (int r = 0; r < 4; r++) acc[mi][ni][r] = 0.0f;

    auto load_chunk = [&](int kc, int s) {
        __half* dA = dyn + s * STG;
        __half* dB = dA + AS;
        const __half* ap = A + (size_t)row0 * FEAT + kc * 64;
        const __half* bp = B + (size_t)col0 * FEAT + kc * 64;
#pragma unroll
        for (int j = 0; j < 2; j++) {
            int row = lr + j * 64;
            cpa16(smem_u32(dA + row * SPAD + lc), ap + (size_t)row * FEAT + lc);
        }
#pragma unroll
        for (int j = 0; j < BN / 64; j++) {
            int row = lr + j * 64;
            cpa16(smem_u32(dB + row * SPAD + lc), bp + (size_t)row * FEAT + lc);
        }
        asm volatile("cp.async.commit_group;" ::: "memory");
    };

    load_chunk(0, 0);
    load_chunk(1, 1);

#pragma unroll
    for (int kc = 0; kc < 4; kc++) {
        const int s = kc & 1;
        if (kc < 3) asm volatile("cp.async.wait_group 1;" ::: "memory");
        else        asm volatile("cp.async.wait_group 0;" ::: "memory");
        __syncthreads();

        __half* dA = dyn + s * STG;
        __half* dB = dA + AS;

#pragma unroll
        for (int ks = 0; ks < 4; ks++) {
            const int k0 = ks << 4;
            const int arow = wm0 + (lane & 15);
            const int acol = k0 + ((lane >> 4) << 3);
            const int brow = wn0 + (lane & 7) + ((lane >> 4) << 3);
            const int bcol = k0 + (((lane >> 3) & 1) << 3);

            uint32_t a[2][4], b[NF * 2];
#pragma unroll
            for (int mi = 0; mi < 2; mi++) {
                uint32_t ad = smem_u32(dA + (arow + mi * 16) * SPAD + acol);
                asm volatile("ldmatrix.sync.aligned.m8n8.x4.shared.b16 {%0,%1,%2,%3}, [%4];"
                             : "=r"(a[mi][0]), "=r"(a[mi][1]), "=r"(a[mi][2]), "=r"(a[mi][3])
                             : "r"(ad));
            }
#pragma unroll
            for (int nb = 0; nb < NF / 2; nb++) {
                uint32_t ad = smem_u32(dB + (brow + nb * 16) * SPAD + bcol);
                asm volatile("ldmatrix.sync.aligned.m8n8.x4.shared.b16 {%0,%1,%2,%3}, [%4];"
                             : "=r"(b[nb * 4 + 0]), "=r"(b[nb * 4 + 1]),
                               "=r"(b[nb * 4 + 2]), "=r"(b[nb * 4 + 3])
                             : "r"(ad));
            }
#pragma unroll
            for (int mi = 0; mi < 2; mi++)
#pragma unroll
                for (int ni = 0; ni < NF; ni++)
                    asm volatile(
                        "mma.sync.aligned.m16n8k16.row.col.f32.f16.f16.f32 "
                        "{%0,%1,%2,%3}, {%4,%5,%6,%7}, {%8,%9}, {%0,%1,%2,%3};"
                        : "+f"(acc[mi][ni][0]), "+f"(acc[mi][ni][1]),
                          "+f"(acc[mi][ni][2]), "+f"(acc[mi][ni][3])
                        : "r"(a[mi][0]), "r"(a[mi][1]), "r"(a[mi][2]), "r"(a[mi][3]),
                          "r"(b[ni * 2]), "r"(b[ni * 2 + 1]));
        }
        __syncthreads();
        if (kc + 2 < 4) load_chunk(kc + 2, s);
    }

    const int crow = lane >> 2;
    const int ccol = (lane & 3) << 1;
#pragma unroll
    for (int mi = 0; mi < 2; mi++)
#pragma unroll
        for (int ni = 0; ni < NF; ni++) {
            int col = col0 + wn0 + ni * 8 + ccol;
#pragma unroll
            for (int h = 0; h < 2; h++) {
                int row = row0 + wm0 + mi * 16 + crow + h * 8;
                __half2 p = __float22half2_rn(
                    make_float2(acc[mi][ni][h * 2 + 0], acc[mi][ni][h * 2 + 1]));
                *reinterpret_cast<uint32_t*>(Y + (size_t)row * NOUT + col) =
                    *reinterpret_cast<uint32_t*>(&p);
            }
        }
}

// ---------------- launch ----------------
extern "C" void kernel_launch(void* const* d_in, const int* in_sizes, int n_in,
                              void* d_out, int out_size) {
    const float* x   = (const float*)d_in[0];
    const int*   src = (const int*)d_in[1];
    const int*   dst = (const int*)d_in[2];
    const float* Ws1 = (const float*)d_in[3];
    const float* Wn1 = (const float*)d_in[4];
    const float* b1  = (const float*)d_in[5];
    const float* Ws2 = (const float*)d_in[6];
    const float* Wn2 = (const float*)d_in[7];
    const float* b2  = (const float*)d_in[8];
    const float* Ws3 = (const float*)d_in[9];
    const float* Wn3 = (const float*)d_in[10];
    const float* b3  = (const float*)d_in[11];
    float* out = (float*)d_out;

    const int N = in_sizes[0] / FEAT;   // 100000
    const int E = in_sizes[1];          // 800000

    __half *yz, *h, *w0, *w1, *w3;
    cudaGetSymbolAddress((void**)&yz, g_yz);
    cudaGetSymbolAddress((void**)&h,  g_h);
    cudaGetSymbolAddress((void**)&w0, g_w);
    cudaGetSymbolAddress((void**)&w3, g_w3);
    w1 = w0 + (size_t)512 * 256;

    constexpr int SM256 = (128 * SPAD + 256 * SPAD) * 2 * 2;  // 110592 B
    constexpr int SM128 = (128 * SPAD + 128 * SPAD) * 2 * 2;  // 73728 B
    cudaFuncSetAttribute(k_mma<256, 8>, cudaFuncAttributeMaxDynamicSharedMemorySize, SM256);
    cudaFuncSetAttribute(k_mma<128, 4>, cudaFuncAttributeMaxDynamicSharedMemorySize, SM128);

    const int ZT = 256;
    const int preBlocks = PRE_CVTX + PRE_DEGI + PRE_W12 + PRE_W12 + 128;

    // fused preprocessing: cvt_x | degi | cvt_w x3
    k_pre<<<preBlocks, ZT>>>(x, dst, Ws1, Wn1, Ws2, Wn2, Ws3, Wn3, N, E);
    k_off<<<NB, 256>>>();
    k_fill<<<(E + ZT - 1) / ZT, ZT>>>(src, dst, E);

    dim3 g12(2, NT);
    dim3 g3(1, NT);
    const int gatherB = (N + 7) / 8;
    const int gather3B = (N + 31) / 32;

    // layer 1
    k_mma<256, 8><<<g12, 512, SM256>>>(h, w0, yz, 512);
    k_gather<<<gatherB, 256>>>(b1, N);

    // layer 2
    k_mma<256, 8><<<g12, 512, SM256>>>(h, w1, yz, 512);
    k_gather<<<gatherB, 256>>>(b2, N);

    // layer 3
    k_mma<128, 4><<<g3, 512, SM128>>>(h, w3, yz, 128);
    k_gather3<<<gather3B, 256>>>(b3, out, N);
}

// round 10
// speedup vs baseline: 1.1539x; 1.1539x over previous
#include <cuda_runtime.h>
#include <cuda_fp16.h>
#include <cstdint>

#define NN   100000
#define MPAD 100096            // 782 * 128
#define FEAT 256
#define NT   782
#define SPAD 72
#define EMAX 800000
#define NB   391               // ceil(NN/256)

// block ranges in k_pre
#define PRE_CVTX 25024         // MPAD*64/256
#define PRE_DEGI 3125
#define PRE_W12  512           // 2*256*256/256

// ---------------- device scratch ----------------
__device__ int   g_degi[NN];           // zero-init; k_off restores zeros
__device__ int   g_ctr;
__device__ float g_inv[NN];
__device__ int   g_off[NN];
__device__ int   g_end[NN];
__device__ int   g_cursor[NN];
__device__ int   g_srcl[EMAX];
__device__ __align__(16) __half g_yz[(size_t)MPAD * 512];
__device__ __align__(16) __half g_h[(size_t)MPAD * FEAT];
__device__ __align__(16) __half g_w[2][512 * 256];
__device__ __align__(16) __half g_w3[128 * 256];

// ---------------- helpers ----------------
__device__ __forceinline__ uint32_t smem_u32(const void* p) {
    uint32_t a;
    asm("{ .reg .u64 t; cvta.to.shared.u64 t, %1; cvt.u32.u64 %0, t; }" : "=r"(a) : "l"(p));
    return a;
}
__device__ __forceinline__ void cpa16(uint32_t dst, const void* src) {
    asm volatile("cp.async.cg.shared.global [%0], [%1], 16;" :: "r"(dst), "l"(src));
}
__device__ __forceinline__ void cvt_w_seg(const float* __restrict__ Ws,
                                          const float* __restrict__ Wn,
                                          int Nw, __half* __restrict__ w, int idx) {
    int n = idx >> 8, k = idx & 255;
    float v = (n < Nw) ? Ws[(size_t)k * Nw + n] : Wn[(size_t)k * Nw + (n - Nw)];
    w[idx] = __float2half_rn(v);
}

// ---------------- fused preprocessing: cvt_x | degi | cvt_w x3 ----------------
__global__ void k_pre(const float* __restrict__ x, const int* __restrict__ dst,
                      const float* __restrict__ Ws1, const float* __restrict__ Wn1,
                      const float* __restrict__ Ws2, const float* __restrict__ Wn2,
                      const float* __restrict__ Ws3, const float* __restrict__ Wn3,
                      int M, int E) {
    int b = blockIdx.x;
    int tid = threadIdx.x;
    if (b == 0 && tid == 0) g_ctr = 0;
    if (b < PRE_CVTX) {
        size_t i4 = (size_t)b * 256 + tid;
        int row = (int)(i4 >> 6);
        float4 v = make_float4(0.f, 0.f, 0.f, 0.f);
        if (row < M) v = reinterpret_cast<const float4*>(x)[i4];
        uint2 o;
        __half2 p0 = __float22half2_rn(make_float2(v.x, v.y));
        __half2 p1 = __float22half2_rn(make_float2(v.z, v.w));
        o.x = *reinterpret_cast<uint32_t*>(&p0);
        o.y = *reinterpret_cast<uint32_t*>(&p1);
        *reinterpret_cast<uint2*>(g_h + i4 * 4) = o;
        return;
    }
    b -= PRE_CVTX;
    if (b < PRE_DEGI) {
        int e = b * 256 + tid;
        if (e < E) atomicAdd(&g_degi[dst[e]], 1);
        return;
    }
    b -= PRE_DEGI;
    if (b < PRE_W12) { cvt_w_seg(Ws1, Wn1, 256, g_w[0], b * 256 + tid); return; }
    b -= PRE_W12;
    if (b < PRE_W12) { cvt_w_seg(Ws2, Wn2, 256, g_w[1], b * 256 + tid); return; }
    b -= PRE_W12;
    cvt_w_seg(Ws3, Wn3, 64, g_w3, b * 256 + tid);
}

// single-pass offsets: block scan + atomic range reservation
__global__ void k_off() {
    __shared__ int s[256];
    __shared__ int base;
    int i = blockIdx.x * 256 + threadIdx.x;
    int deg = (i < NN) ? g_degi[i] : 0;
    s[threadIdx.x] = deg;
    __syncthreads();
    for (int st = 1; st < 256; st <<= 1) {
        int add = (threadIdx.x >= st) ? s[threadIdx.x - st] : 0;
        __syncthreads();
        s[threadIdx.x] += add;
        __syncthreads();
    }
    if (threadIdx.x == 255) base = atomicAdd(&g_ctr, s[255]);
    __syncthreads();
    if (i < NN) {
        int beg = base + s[threadIdx.x] - deg;
        g_off[i] = beg;
        g_end[i] = beg + deg;
        g_cursor[i] = beg;
        g_inv[i] = 1.0f / fmaxf((float)deg, 1.0f);
        g_degi[i] = 0;                    // restore for next replay
    }
}
__global__ void k_fill(const int* __restrict__ src, const int* __restrict__ dst, int E) {
    int e = blockIdx.x * blockDim.x + threadIdx.x;
    if (e < E) {
        int pos = atomicAdd(&g_cursor[dst[e]], 1);
        g_srcl[pos] = src[e];
    }
}

// ---------------- fused gather + combine ----------------
__device__ __forceinline__ void acc8(float* acc, uint4 raw) {
    const __half2* hp = reinterpret_cast<const __half2*>(&raw);
#pragma unroll
    for (int q = 0; q < 4; q++) {
        float2 f = __half22float2(hp[q]);
        acc[q * 2 + 0] += f.x;
        acc[q * 2 + 1] += f.y;
    }
}
// layers 1/2: one warp per node, lane owns 8 cols of 256.
__global__ void k_gather(const float* __restrict__ bias, int M) {
    int wid  = threadIdx.x >> 5;
    int lane = threadIdx.x & 31;
    int node = blockIdx.x * (blockDim.x >> 5) + wid;
    if (node >= M) return;
    int beg = g_off[node], end = g_end[node];
    const __half* z = g_yz + 256 + lane * 8;
    float acc[8] = {0.f, 0.f, 0.f, 0.f, 0.f, 0.f, 0.f, 0.f};
    int j = beg;
    for (; j + 4 <= end; j += 4) {
        int s0 = g_srcl[j], s1 = g_srcl[j + 1];
        int s2 = g_srcl[j + 2], s3 = g_srcl[j + 3];
        uint4 r0 = *reinterpret_cast<const uint4*>(z + (size_t)s0 * 512);
        uint4 r1 = *reinterpret_cast<const uint4*>(z + (size_t)s1 * 512);
        uint4 r2 = *reinterpret_cast<const uint4*>(z + (size_t)s2 * 512);
        uint4 r3 = *reinterpret_cast<const uint4*>(z + (size_t)s3 * 512);
        acc8(acc, r0); acc8(acc, r1); acc8(acc, r2); acc8(acc, r3);
    }
    for (; j < end; j++) {
        int s0 = g_srcl[j];
        uint4 r0 = *reinterpret_cast<const uint4*>(z + (size_t)s0 * 512);
        acc8(acc, r0);
    }
    float inv = g_inv[node];
    uint4 rs = *reinterpret_cast<const uint4*>(g_yz + (size_t)node * 512 + lane * 8);
    const __half2* sp = reinterpret_cast<const __half2*>(&rs);
    float4 bva = *reinterpret_cast<const float4*>(bias + lane * 8);
    float4 bvb = *reinterpret_cast<const float4*>(bias + lane * 8 + 4);
    float bv[8] = {bva.x, bva.y, bva.z, bva.w, bvb.x, bvb.y, bvb.z, bvb.w};
    float v[8];
#pragma unroll
    for (int q = 0; q < 4; q++) {
        float2 ys = __half22float2(sp[q]);
        v[q * 2 + 0] = fmaxf(ys.x + inv * acc[q * 2 + 0] + bv[q * 2 + 0], 0.f);
        v[q * 2 + 1] = fmaxf(ys.y + inv * acc[q * 2 + 1] + bv[q * 2 + 1], 0.f);
    }
    uint4 o;
    __half2 p0 = __float22half2_rn(make_float2(v[0], v[1]));
    __half2 p1 = __float22half2_rn(make_float2(v[2], v[3]));
    __half2 p2 = __float22half2_rn(make_float2(v[4], v[5]));
    __half2 p3 = __float22half2_rn(make_float2(v[6], v[7]));
    o.x = *reinterpret_cast<uint32_t*>(&p0);
    o.y = *reinterpret_cast<uint32_t*>(&p1);
    o.z = *reinterpret_cast<uint32_t*>(&p2);
    o.w = *reinterpret_cast<uint32_t*>(&p3);
    *reinterpret_cast<uint4*>(g_h + (size_t)node * 256 + lane * 8) = o;
}
// layer 3: 8 lanes per node (4 nodes/warp), lane owns 8 of 64 cols, fp32 out.
__global__ void k_gather3(const float* __restrict__ bias, float* __restrict__ out, int M) {
    int wid  = threadIdx.x >> 5;
    int lane = threadIdx.x & 31;
    int node = (blockIdx.x * (blockDim.x >> 5) + wid) * 4 + (lane >> 3);
    int sub  = lane & 7;
    if (node >= M) return;
    int beg = g_off[node], end = g_end[node];
    const __half* z = g_yz + 64 + sub * 8;
    float acc[8] = {0.f, 0.f, 0.f, 0.f, 0.f, 0.f, 0.f, 0.f};
    int j = beg;
    for (; j + 4 <= end; j += 4) {
        int s0 = g_srcl[j], s1 = g_srcl[j + 1];
        int s2 = g_srcl[j + 2], s3 = g_srcl[j + 3];
        uint4 r0 = *reinterpret_cast<const uint4*>(z + (size_t)s0 * 128);
        uint4 r1 = *reinterpret_cast<const uint4*>(z + (size_t)s1 * 128);
        uint4 r2 = *reinterpret_cast<const uint4*>(z + (size_t)s2 * 128);
        uint4 r3 = *reinterpret_cast<const uint4*>(z + (size_t)s3 * 128);
        acc8(acc, r0); acc8(acc, r1); acc8(acc, r2); acc8(acc, r3);
    }
    for (; j < end; j++) {
        int s0 = g_srcl[j];
        uint4 r0 = *reinterpret_cast<const uint4*>(z + (size_t)s0 * 128);
        acc8(acc, r0);
    }
    float inv = g_inv[node];
    uint4 rs = *reinterpret_cast<const uint4*>(g_yz + (size_t)node * 128 + sub * 8);
    const __half2* sp = reinterpret_cast<const __half2*>(&rs);
    float4 bva = *reinterpret_cast<const float4*>(bias + sub * 8);
    float4 bvb = *reinterpret_cast<const float4*>(bias + sub * 8 + 4);
    float bv[8] = {bva.x, bva.y, bva.z, bva.w, bvb.x, bvb.y, bvb.z, bvb.w};
    float v[8];
#pragma unroll
    for (int q = 0; q < 4; q++) {
        float2 ys = __half22float2(sp[q]);
        v[q * 2 + 0] = ys.x + inv * acc[q * 2 + 0] + bv[q * 2 + 0];
        v[q * 2 + 1] = ys.y + inv * acc[q * 2 + 1] + bv[q * 2 + 1];
    }
    float* op = out + (size_t)node * 64 + sub * 8;
    *reinterpret_cast<float4*>(op)     = make_float4(v[0], v[1], v[2], v[3]);
    *reinterpret_cast<float4*>(op + 4) = make_float4(v[4], v[5], v[6], v[7]);
}

// ---------------- fp16 HMMA GEMM: 256 threads, 8 warps (2m x 4n), warp tile 64x32 ----------------
// CTA tile 128 x 128, BK=64, 3-stage cp.async, 2 CTAs/SM.
__global__ __launch_bounds__(256, 2) void k_mma(
    const __half* __restrict__ A, const __half* __restrict__ B,
    __half* __restrict__ Y, int NOUT)
{
    extern __shared__ __half dyn[];
    constexpr int AS  = 128 * SPAD;
    constexpr int STG = 2 * AS;           // A tile + B tile (both 128 rows)

    const int t    = threadIdx.x;
    const int wid  = t >> 5;
    const int lane = t & 31;
    const int wm0  = (wid >> 2) << 6;     // 0 or 64
    const int wn0  = (wid & 3) << 5;      // 0,32,64,96
    const int row0 = blockIdx.y * 128;
    const int col0 = blockIdx.x * 128;

    const int lr = t >> 3;                // 0..31
    const int lc = (t & 7) << 3;          // 0..56

    float acc[4][4][4];
#pragma unroll
    for (int mi = 0; mi < 4; mi++)
#pragma unroll
        for (int ni = 0; ni < 4; ni++)
#pragma unroll
            for (int r = 0; r < 4; r++) acc[mi][ni][r] = 0.0f;

    auto load_chunk = [&](int kc, int s) {
        __half* dA = dyn + s * STG;
        __half* dB = dA + AS;
        const __half* ap = A + (size_t)row0 * FEAT + kc * 64;
        const __half* bp = B + (size_t)col0 * FEAT + kc * 64;
#pragma unroll
        for (int j = 0; j < 4; j++) {
            int row = lr + j * 32;
            cpa16(smem_u32(dA + row * SPAD + lc), ap + (size_t)row * FEAT + lc);
            cpa16(smem_u32(dB + row * SPAD + lc), bp + (size_t)row * FEAT + lc);
        }
        asm volatile("cp.async.commit_group;" ::: "memory");
    };

    load_chunk(0, 0);
    load_chunk(1, 1);

#pragma unroll
    for (int kc = 0; kc < 4; kc++) {
        const int s = kc % 3;
        if (kc + 2 < 4) {
            load_chunk(kc + 2, (kc + 2) % 3);
            asm volatile("cp.async.wait_group 2;" ::: "memory");
        } else if (kc + 1 < 4) {
            asm volatile("cp.async.wait_group 1;" ::: "memory");
        } else {
            asm volatile("cp.async.wait_group 0;" ::: "memory");
        }
        __syncthreads();

        __half* dA = dyn + s * STG;
        __half* dB = dA + AS;

#pragma unroll
        for (int ks = 0; ks < 4; ks++) {
            const int k0 = ks << 4;
            const int arow = wm0 + (lane & 15);
            const int acol = k0 + ((lane >> 4) << 3);
            const int brow = wn0 + (lane & 7) + ((lane >> 4) << 3);
            const int bcol = k0 + (((lane >> 3) & 1) << 3);

            uint32_t a[4][4], b[8];
#pragma unroll
            for (int mi = 0; mi < 4; mi++) {
                uint32_t ad = smem_u32(dA + (arow + mi * 16) * SPAD + acol);
                asm volatile("ldmatrix.sync.aligned.m8n8.x4.shared.b16 {%0,%1,%2,%3}, [%4];"
                             : "=r"(a[mi][0]), "=r"(a[mi][1]), "=r"(a[mi][2]), "=r"(a[mi][3])
                             : "r"(ad));
            }
#pragma unroll
            for (int nb = 0; nb < 2; nb++) {
                uint32_t ad = smem_u32(dB + (brow + nb * 16) * SPAD + bcol);
                asm volatile("ldmatrix.sync.aligned.m8n8.x4.shared.b16 {%0,%1,%2,%3}, [%4];"
                             : "=r"(b[nb * 4 + 0]), "=r"(b[nb * 4 + 1]),
                               "=r"(b[nb * 4 + 2]), "=r"(b[nb * 4 + 3])
                             : "r"(ad));
            }
#pragma unroll
            for (int mi = 0; mi < 4; mi++)
#pragma unroll
                for (int ni = 0; ni < 4; ni++)
                    asm volatile(
                        "mma.sync.aligned.m16n8k16.row.col.f32.f16.f16.f32 "
                        "{%0,%1,%2,%3}, {%4,%5,%6,%7}, {%8,%9}, {%0,%1,%2,%3};"
                        : "+f"(acc[mi][ni][0]), "+f"(acc[mi][ni][1]),
                          "+f"(acc[mi][ni][2]), "+f"(acc[mi][ni][3])
                        : "r"(a[mi][0]), "r"(a[mi][1]), "r"(a[mi][2]), "r"(a[mi][3]),
                          "r"(b[ni * 2]), "r"(b[ni * 2 + 1]));
        }
        __syncthreads();
    }

    const int crow = lane >> 2;
    const int ccol = (lane & 3) << 1;
#pragma unroll
    for (int mi = 0; mi < 4; mi++)
#pragma unroll
        for (int ni = 0; ni < 4; ni++) {
            int col = col0 + wn0 + ni * 8 + ccol;
#pragma unroll
            for (int h = 0; h < 2; h++) {
                int row = row0 + wm0 + mi * 16 + crow + h * 8;
                __half2 p = __float22half2_rn(
                    make_float2(acc[mi][ni][h * 2 + 0], acc[mi][ni][h * 2 + 1]));
                *reinterpret_cast<uint32_t*>(Y + (size_t)row * NOUT + col) =
                    *reinterpret_cast<uint32_t*>(&p);
            }
        }
}

// ---------------- launch ----------------
extern "C" void kernel_launch(void* const* d_in, const int* in_sizes, int n_in,
                              void* d_out, int out_size) {
    const float* x   = (const float*)d_in[0];
    const int*   src = (const int*)d_in[1];
    const int*   dst = (const int*)d_in[2];
    const float* Ws1 = (const float*)d_in[3];
    const float* Wn1 = (const float*)d_in[4];
    const float* b1  = (const float*)d_in[5];
    const float* Ws2 = (const float*)d_in[6];
    const float* Wn2 = (const float*)d_in[7];
    const float* b2  = (const float*)d_in[8];
    const float* Ws3 = (const float*)d_in[9];
    const float* Wn3 = (const float*)d_in[10];
    const float* b3  = (const float*)d_in[11];
    float* out = (float*)d_out;

    const int N = in_sizes[0] / FEAT;   // 100000
    const int E = in_sizes[1];          // 800000

    __half *yz, *h, *w0, *w1, *w3;
    cudaGetSymbolAddress((void**)&yz, g_yz);
    cudaGetSymbolAddress((void**)&h,  g_h);
    cudaGetSymbolAddress((void**)&w0, g_w);
    cudaGetSymbolAddress((void**)&w3, g_w3);
    w1 = w0 + (size_t)512 * 256;

    constexpr int SM = 128 * SPAD * 2 * 3 * 2;   // 110592 B (3 stages x (A+B) x fp16)
    cudaFuncSetAttribute(k_mma, cudaFuncAttributeMaxDynamicSharedMemorySize, SM);

    const int ZT = 256;
    const int preBlocks = PRE_CVTX + PRE_DEGI + PRE_W12 + PRE_W12 + 128;

    // fused preprocessing: cvt_x | degi | cvt_w x3
    k_pre<<<preBlocks, ZT>>>(x, dst, Ws1, Wn1, Ws2, Wn2, Ws3, Wn3, N, E);
    k_off<<<NB, 256>>>();
    k_fill<<<(E + ZT - 1) / ZT, ZT>>>(src, dst, E);

    dim3 g12(4, NT);
    dim3 g3(1, NT);
    const int gatherB = (N + 7) / 8;
    const int gather3B = (N + 31) / 32;

    // layer 1
    k_mma<<<g12, 256, SM>>>(h, w0, yz, 512);
    k_gather<<<gatherB, 256>>>(b1, N);

    // layer 2
    k_mma<<<g12, 256, SM>>>(h, w1, yz, 512);
    k_gather<<<gatherB, 256>>>(b2, N);

    // layer 3
    k_mma<<<g3, 256, SM>>>(h, w3, yz, 128);
    k_gather3<<<gather3B, 256>>>(b3, out, N);
}